// round 15
// baseline (speedup 1.0000x reference)
#include <cuda_runtime.h>
#include <cuda_fp16.h>
#include <cstdint>

// ===========================================================================
// EntmaxAttention B=8, N=1024, C=1024, H=8, D=128, alpha=1.5
// out  = [8,1024,1024]   -> d_out[0..8388608)
// attn = [8,8,1024,1024] -> d_out[8388608..75497472)
//
// Base sm_103: GEMMs via mma.sync m16n8k16 fp16 (HMMA).
// Main products: fp32 accumulators (half-rate). Correction products
// (~2^-11 scale): fp16 accumulators (full rate), added in epilogue.
// Q proj: 3 products (1 fp32 + 2 fp16-acc). K/scores/out: 2 products
// (1 fp32 + 1 fp16-acc). V/ctx: 1 product fp32.
// 128x128 CTA tiles, 256 thr, 64x32 warp tiles, 2 CTA/SM (reg cap 128).
// ===========================================================================

#define BDIM 8
#define HDIM 8
#define NDIM 1024
#define CDIM 1024
#define DDIM 128
#define OUT_ELEMS (BDIM*NDIM*CDIM)
#define HEADS (BDIM*HDIM)

__device__ __forceinline__ uint32_t smem_u32(const void* p) {
    uint32_t a;
    asm("{ .reg .u64 t; cvta.to.shared.u64 t, %1; cvt.u32.u64 %0, t; }"
        : "=r"(a) : "l"(p));
    return a;
}
__device__ __forceinline__ void cpa16(uint32_t dst, const void* src) {
    asm volatile("cp.async.cg.shared.global [%0], [%1], 16;" :: "r"(dst), "l"(src));
}
__device__ __forceinline__ void cpa_commit() {
    asm volatile("cp.async.commit_group;" ::: "memory");
}
template<int N>
__device__ __forceinline__ void cpa_wait() {
    asm volatile("cp.async.wait_group %0;" :: "n"(N) : "memory");
}
// fp32-accumulator HMMA (main product)
__device__ __forceinline__ void mma16816(float* d, const uint32_t* a, const uint32_t* b) {
    asm volatile("mma.sync.aligned.m16n8k16.row.col.f32.f16.f16.f32 "
        "{%0,%1,%2,%3}, {%4,%5,%6,%7}, {%8,%9}, {%0,%1,%2,%3};"
        : "+f"(d[0]), "+f"(d[1]), "+f"(d[2]), "+f"(d[3])
        : "r"(a[0]), "r"(a[1]), "r"(a[2]), "r"(a[3]), "r"(b[0]), "r"(b[1]));
}
// fp16-accumulator HMMA (small correction terms, full rate)
__device__ __forceinline__ void mma16816h(uint32_t* d, const uint32_t* a, const uint32_t* b) {
    asm volatile("mma.sync.aligned.m16n8k16.row.col.f16.f16.f16.f16 "
        "{%0,%1}, {%2,%3,%4,%5}, {%6,%7}, {%0,%1};"
        : "+r"(d[0]), "+r"(d[1])
        : "r"(a[0]), "r"(a[1]), "r"(a[2]), "r"(a[3]), "r"(b[0]), "r"(b[1]));
}
__device__ __forceinline__ void ldm_x4(uint32_t* r, uint32_t addr) {
    asm volatile("ldmatrix.sync.aligned.m8n8.x4.shared.b16 {%0,%1,%2,%3}, [%4];"
        : "=r"(r[0]), "=r"(r[1]), "=r"(r[2]), "=r"(r[3]) : "r"(addr));
}

// ------------------------- scratch (device globals) ------------------------
__device__ __half g_xh[OUT_ELEMS],  g_xl[OUT_ELEMS];
__device__ __half g_wqh[CDIM*CDIM], g_wql[CDIM*CDIM];
__device__ __half g_wkh[CDIM*CDIM], g_wkl[CDIM*CDIM];
__device__ __half g_wvt[CDIM*CDIM];
__device__ __half g_wot[CDIM*CDIM];
__device__ __half g_qh[OUT_ELEMS],  g_ql[OUT_ELEMS];      // [BH,N,D] split
__device__ __half g_kh[OUT_ELEMS];                        // [BH,N,D] single
__device__ __half g_vt[OUT_ELEMS];                        // [BH,D,N] single
__device__ __half g_ah[(size_t)HEADS*NDIM*NDIM];          // attn fp16
__device__ __half g_ch[OUT_ELEMS],  g_cl[OUT_ELEMS];      // ctx [B,N,C] split

// ------------------------- prep kernels -------------------------------------
__global__ void __launch_bounds__(256) split_kernel(
    const float* __restrict__ src, __half* __restrict__ hi,
    __half* __restrict__ lo, int n)
{
    int i = blockIdx.x * 256 + threadIdx.x;
    if (i < n) {
        float v = src[i];
        __half h = __float2half(v);
        hi[i] = h;
        lo[i] = __float2half(v - __half2float(h));
    }
}

__global__ void __launch_bounds__(1024) splitT2_kernel(
    const float* __restrict__ W0, const float* __restrict__ W1,
    __half* __restrict__ h0, __half* __restrict__ l0,
    __half* __restrict__ h1, __half* __restrict__ l1)
{
    const float* W = blockIdx.z ? W1 : W0;
    __half* hiT = blockIdx.z ? h1 : h0;
    __half* loT = blockIdx.z ? l1 : l0;
    __shared__ float t[32][33];
    int bx = blockIdx.x * 32, by = blockIdx.y * 32;
    int x = threadIdx.x, y = threadIdx.y;
    t[y][x] = W[(size_t)(by + y) * CDIM + bx + x];
    __syncthreads();
    float v = t[x][y];
    __half h = __float2half(v);
    size_t o = (size_t)(bx + y) * CDIM + by + x;
    hiT[o] = h;
    loT[o] = __float2half(v - __half2float(h));
}

__global__ void __launch_bounds__(1024) cvtT2_kernel(
    const float* __restrict__ W0, const float* __restrict__ W1,
    __half* __restrict__ t0, __half* __restrict__ t1)
{
    const float* W = blockIdx.z ? W1 : W0;
    __half* hT = blockIdx.z ? t1 : t0;
    __shared__ float t[32][33];
    int bx = blockIdx.x * 32, by = blockIdx.y * 32;
    int x = threadIdx.x, y = threadIdx.y;
    t[y][x] = W[(size_t)(by + y) * CDIM + bx + x];
    __syncthreads();
    hT[(size_t)(bx + y) * CDIM + by + x] = __float2half(t[x][y]);
}

// ------------------------- generic HMMA GEMM --------------------------------
// D[m,n] = sum_k A[m,k]*B[n,k]  (both K-major), 128x128 CTA tile, 256 thr,
// 64x32 warp tiles.
// NPROD 3: AhBh(f32) + [AhBl+AlBh](f16 acc), BK=32, NSTAGE=2 (80KB)
// NPROD 2: AhB(f32) + AlB(f16 acc),          BK=64, NSTAGE=2 (110.6KB)
// NPROD 1: AB(f32),                          BK=64, NSTAGE=3 (110.6KB)
// MODE 0: Q proj  -> hi/lo fp16 [B,H,N,D] (+bias)
// MODE 1: V proj  -> single fp16 vT [B,H,D,N] (+bias)
// MODE 2: scores  -> fp32*scale at outF[z<<20]
// MODE 3: ctx     -> hi/lo fp16 ctx [B,N,C]
// MODE 4: out proj-> fp32+bias at outF
// MODE 5: K proj  -> single fp16 [B,H,N,D] (+bias)
struct GP {
    const __half *Ah, *Al, *Bh, *Bl;
    long long strideAz, strideBz;
    int lda, ldb, K;
    const float* bias;
    float scale;
    float* outF;
    __half *outH, *outL;
};

template<int MODE, int NPROD>
__global__ void __launch_bounds__(256, 2) gemm_hmma(GP p)
{
    constexpr int BK     = (NPROD == 3) ? 32 : 64;
    constexpr int KSTEPS = BK / 16;
    constexpr int ROWBk  = (NPROD == 3) ? 80 : 144;
    constexpr uint32_t TILEB = 128u * ROWBk;
    constexpr int NT = (NPROD == 3) ? 4 : ((NPROD == 2) ? 3 : 2);
    constexpr int NSTAGE = (NPROD == 1) ? 3 : 2;
    constexpr uint32_t STAGE = NT * TILEB;
    constexpr uint32_t BOFF = (NPROD == 1) ? TILEB : 2u * TILEB;
    constexpr int CPR = BK / 8;

    extern __shared__ char smem[];
    const uint32_t sbase = smem_u32(smem);
    const int tid = threadIdx.x;
    const int wid = tid >> 5;
    const int lane = tid & 31;
    const int g = lane >> 2;
    const int tq = lane & 3;
    const int warp_m = (wid >> 2) * 64;
    const int warp_n = (wid & 3) * 32;
    const int z = blockIdx.z;
    const int row0 = blockIdx.y * 128;
    const int col0 = blockIdx.x * 128;

    const __half* Ah = p.Ah + (size_t)z * p.strideAz;
    const __half* Al = (NPROD >= 2) ? (p.Al + (size_t)z * p.strideAz) : nullptr;
    const __half* Bh = p.Bh + (size_t)z * p.strideBz;
    const __half* Bl = (NPROD == 3) ? (p.Bl + (size_t)z * p.strideBz) : nullptr;

    float acc[4][4][4];
    uint32_t hacc[4][4][2];   // fp16x2 correction accumulators (NPROD>=2)
    #pragma unroll
    for (int i = 0; i < 4; i++)
        #pragma unroll
        for (int j = 0; j < 4; j++) {
            #pragma unroll
            for (int e = 0; e < 4; e++) acc[i][j][e] = 0.f;
            hacc[i][j][0] = 0u; hacc[i][j][1] = 0u;
        }

    const int nchunk = p.K / BK;

    const uint32_t a_off = (uint32_t)((warp_m + (lane & 15)) * ROWBk + (lane >> 4) * 16);
    const uint32_t b_off = (uint32_t)((warp_n + (lane & 7) + ((lane >> 4) << 3)) * ROWBk
                                      + ((lane >> 3) & 1) * 16);

    auto prefetch = [&](int c) {
        int s = c % NSTAGE;
        int k0 = c * BK;
        uint32_t sb = sbase + s * STAGE;
        #pragma unroll
        for (int it = 0; it < KSTEPS; it++) {
            int id = tid + it * 256;
            int r = id / CPR;
            int ch = id % CPR;
            uint32_t doff = (uint32_t)(r * ROWBk + ch * 16);
            size_t ga = (size_t)(row0 + r) * p.lda + k0 + ch * 8;
            size_t gb = (size_t)(col0 + r) * p.ldb + k0 + ch * 8;
            cpa16(sb + doff, Ah + ga);
            if (NPROD >= 2) cpa16(sb + TILEB + doff, Al + ga);
            cpa16(sb + BOFF + doff, Bh + gb);
            if (NPROD == 3) cpa16(sb + BOFF + TILEB + doff, Bl + gb);
        }
        cpa_commit();
    };

    prefetch(0);
    if (NSTAGE == 3 && nchunk > 1) prefetch(1);

    for (int c = 0; c < nchunk; c++) {
        if (NSTAGE == 2) {
            cpa_wait<0>();
            __syncthreads();
            if (c + 1 < nchunk) prefetch(c + 1);
        } else {
            if (c + 1 < nchunk) cpa_wait<1>(); else cpa_wait<0>();
            __syncthreads();
            if (c + 2 < nchunk) prefetch(c + 2);
        }

        uint32_t stg = sbase + (uint32_t)((c % NSTAGE) * STAGE);

        #pragma unroll
        for (int s16 = 0; s16 < KSTEPS; s16++) {
            const uint32_t koffb = (uint32_t)(s16 * 32);

            // B fragments for this k-step
            uint32_t bh[4][2], bl[4][2];
            #pragma unroll
            for (int jp = 0; jp < 2; jp++) {
                uint32_t ba = stg + BOFF + b_off + koffb + (uint32_t)(jp * 16 * ROWBk);
                uint32_t r4[4];
                ldm_x4(r4, ba);
                bh[jp*2][0] = r4[0]; bh[jp*2][1] = r4[1];
                bh[jp*2+1][0] = r4[2]; bh[jp*2+1][1] = r4[3];
                if (NPROD == 3) {
                    ldm_x4(r4, ba + TILEB);
                    bl[jp*2][0] = r4[0]; bl[jp*2][1] = r4[1];
                    bl[jp*2+1][0] = r4[2]; bl[jp*2+1][1] = r4[3];
                }
            }

            // A fragments loaded per i-tile (no double-buffer: reg budget)
            #pragma unroll
            for (int i = 0; i < 4; i++) {
                uint32_t aa = stg + a_off + koffb + (uint32_t)(i * 16 * ROWBk);
                uint32_t ah[4], al[4];
                ldm_x4(ah, aa);
                if (NPROD >= 2) ldm_x4(al, aa + TILEB);
                #pragma unroll
                for (int j = 0; j < 4; j++) {
                    mma16816(acc[i][j], ah, bh[j]);
                    if (NPROD == 3) mma16816h(hacc[i][j], ah, bl[j]);
                    if (NPROD >= 2) mma16816h(hacc[i][j], al, bh[j]);
                }
            }
        }
    }

    // --- epilogue (paired-column vector stores, + fp16 correction add) ---
    #pragma unroll
    for (int i = 0; i < 4; i++) {
        #pragma unroll
        for (int j = 0; j < 4; j++) {
            #pragma unroll
            for (int eh = 0; eh < 2; eh++) {
                int m  = row0 + warp_m + i*16 + g + eh*8;
                int cc = col0 + warp_n + j*8 + tq*2;
                float v0 = acc[i][j][eh*2 + 0];
                float v1 = acc[i][j][eh*2 + 1];
                if (NPROD >= 2) {
                    __half2 hc = *reinterpret_cast<__half2*>(&hacc[i][j][eh]);
                    v0 += __low2float(hc);
                    v1 += __high2float(hc);
                }
                if (MODE == 0) {
                    v0 += p.bias[cc]; v1 += p.bias[cc + 1];
                    int b = m >> 10, nn = m & 1023;
                    int h = cc >> 7, d = cc & 127;
                    size_t o = ((size_t)(((b*8 + h) << 10) + nn)) * 128 + d;
                    __half h0 = __float2half(v0), h1 = __float2half(v1);
                    *(__half2*)&p.outH[o] = __halves2half2(h0, h1);
                    *(__half2*)&p.outL[o] = __halves2half2(
                        __float2half(v0 - __half2float(h0)),
                        __float2half(v1 - __half2float(h1)));
                } else if (MODE == 1) {
                    v0 += p.bias[cc]; v1 += p.bias[cc + 1];
                    int b = m >> 10, nn = m & 1023;
                    int h = cc >> 7, d = cc & 127;
                    size_t o = ((size_t)(((b*8 + h) << 7) + d)) * 1024 + nn;
                    p.outH[o] = __float2half(v0);
                    p.outH[o + 1024] = __float2half(v1);
                } else if (MODE == 2) {
                    float2 o2 = make_float2(v0 * p.scale, v1 * p.scale);
                    *(float2*)&p.outF[((size_t)z << 20) + (size_t)m * 1024 + cc] = o2;
                } else if (MODE == 3) {
                    int b = z >> 3, h = z & 7;
                    size_t o = ((size_t)((b << 10) + m)) * 1024 + h * 128 + cc;
                    __half h0 = __float2half(v0), h1 = __float2half(v1);
                    *(__half2*)&p.outH[o] = __halves2half2(h0, h1);
                    *(__half2*)&p.outL[o] = __halves2half2(
                        __float2half(v0 - __half2float(h0)),
                        __float2half(v1 - __half2float(h1)));
                } else if (MODE == 4) {
                    float2 o2 = make_float2(v0 + p.bias[cc], v1 + p.bias[cc + 1]);
                    *(float2*)&p.outF[(size_t)m * 1024 + cc] = o2;
                } else {  // MODE 5: K proj single fp16 [B,H,N,D]
                    v0 += p.bias[cc]; v1 += p.bias[cc + 1];
                    int b = m >> 10, nn = m & 1023;
                    int h = cc >> 7, d = cc & 127;
                    size_t o = ((size_t)(((b*8 + h) << 10) + nn)) * 128 + d;
                    *(__half2*)&p.outH[o] =
                        __halves2half2(__float2half(v0), __float2half(v1));
                }
            }
        }
    }
}

// ------------------------- entmax (in place, + fp16 attn) ------------------
__global__ void __launch_bounds__(256) entmax_kernel(
    float* __restrict__ attn, __half* __restrict__ ah)
{
    int gwarp = (blockIdx.x * blockDim.x + threadIdx.x) >> 5;
    int lane  = threadIdx.x & 31;
    size_t rbase = (size_t)gwarp * 1024;
    float* row = attn + rbase;
    const float4* rv = (const float4*)row;

    float xm[32];
    #pragma unroll
    for (int i = 0; i < 8; i++) {
        float4 v = rv[i*32 + lane];
        xm[i*4+0] = 0.5f * v.x; xm[i*4+1] = 0.5f * v.y;
        xm[i*4+2] = 0.5f * v.z; xm[i*4+3] = 0.5f * v.w;
    }

    float mx = xm[0];
    #pragma unroll
    for (int i = 1; i < 32; i++) mx = fmaxf(mx, xm[i]);
    #pragma unroll
    for (int o = 16; o > 0; o >>= 1)
        mx = fmaxf(mx, __shfl_xor_sync(0xffffffffu, mx, o));

    float tau_lo = mx - 1.0f;
    float dm = 1.0f - 0.03125f;

    float s0 = 0.f, s1 = 0.f, s2 = 0.f, s3 = 0.f;
    #pragma unroll
    for (int i = 0; i < 8; i++) {
        float t0 = fmaxf(xm[i*4+0] - tau_lo, 0.f);
        float t1 = fmaxf(xm[i*4+1] - tau_lo, 0.f);
        float t2 = fmaxf(xm[i*4+2] - tau_lo, 0.f);
        float t3 = fmaxf(xm[i*4+3] - tau_lo, 0.f);
        s0 = fmaf(t0, t0, s0); s1 = fmaf(t1, t1, s1);
        s2 = fmaf(t2, t2, s2); s3 = fmaf(t3, t3, s3);
    }
    float s = (s0 + s1) + (s2 + s3);
    #pragma unroll
    for (int o = 16; o > 0; o >>= 1)
        s += __shfl_xor_sync(0xffffffffu, s, o);
    float f_lo = s - 1.0f;

    float tau_m = tau_lo;
    #pragma unroll 1
    for (int it = 0; it < 16; it++) {
        dm *= 0.5f;
        tau_m = tau_lo + dm;
        float f0 = 0.f, f1 = 0.f, f2 = 0.f, f3 = 0.f;
        #pragma unroll
        for (int i = 0; i < 8; i++) {
            float t0 = fmaxf(xm[i*4+0] - tau_m, 0.f);
            float t1 = fmaxf(xm[i*4+1] - tau_m, 0.f);
            float t2 = fmaxf(xm[i*4+2] - tau_m, 0.f);
            float t3 = fmaxf(xm[i*4+3] - tau_m, 0.f);
            f0 = fmaf(t0, t0, f0); f1 = fmaf(t1, t1, f1);
            f2 = fmaf(t2, t2, f2); f3 = fmaf(t3, t3, f3);
        }
        float fs = (f0 + f1) + (f2 + f3);
        #pragma unroll
        for (int o = 16; o > 0; o >>= 1)
            fs += __shfl_xor_sync(0xffffffffu, fs, o);
        if ((fs - 1.0f) * f_lo >= 0.f) tau_lo = tau_m;
    }

    float pv[32];
    float psum = 0.f;
    #pragma unroll
    for (int i = 0; i < 32; i++) {
        float t = fmaxf(xm[i] - tau_m, 0.f);
        pv[i] = t * t;
        psum += pv[i];
    }
    #pragma unroll
    for (int o = 16; o > 0; o >>= 1)
        psum += __shfl_xor_sync(0xffffffffu, psum, o);
    float inv = 1.0f / psum;

    float4* wv = (float4*)row;
    #pragma unroll
    for (int i = 0; i < 8; i++) {
        float4 o;
        o.x = pv[i*4+0] * inv; o.y = pv[i*4+1] * inv;
        o.z = pv[i*4+2] * inv; o.w = pv[i*4+3] * inv;
        wv[i*32 + lane] = o;
        __half2 h01 = __halves2half2(__float2half(o.x), __float2half(o.y));
        __half2 h23 = __halves2half2(__float2half(o.z), __float2half(o.w));
        size_t hi = rbase + (size_t)i*128 + lane*4;
        *(__half2*)&ah[hi]     = h01;
        *(__half2*)&ah[hi + 2] = h23;
    }
}

// ---------------------------------------------------------------------------
extern "C" void kernel_launch(void* const* d_in, const int* in_sizes, int n_in,
                              void* d_out, int out_size)
{
    const float* x  = (const float*)d_in[0];
    const float* Wq = (const float*)d_in[1];
    const float* bq = (const float*)d_in[2];
    const float* Wk = (const float*)d_in[3];
    const float* bk = (const float*)d_in[4];
    const float* Wv = (const float*)d_in[5];
    const float* bv = (const float*)d_in[6];
    const float* Wo = (const float*)d_in[7];
    const float* bo = (const float*)d_in[8];

    float* out  = (float*)d_out;
    float* attn = out + OUT_ELEMS;

    const int SMEM3 = 2 * 4 * 10240;   // 81920   (2 CTA/SM)
    const int SMEM2 = 2 * 3 * 18432;   // 110592  (2 CTA/SM)
    const int SMEM1 = 3 * 2 * 18432;   // 110592  (2 CTA/SM)
    cudaFuncSetAttribute((const void*)gemm_hmma<0,3>, cudaFuncAttributeMaxDynamicSharedMemorySize, SMEM3);
    cudaFuncSetAttribute((const void*)gemm_hmma<5,2>, cudaFuncAttributeMaxDynamicSharedMemorySize, SMEM2);
    cudaFuncSetAttribute((const void*)gemm_hmma<1,1>, cudaFuncAttributeMaxDynamicSharedMemorySize, SMEM1);
    cudaFuncSetAttribute((const void*)gemm_hmma<2,2>, cudaFuncAttributeMaxDynamicSharedMemorySize, SMEM2);
    cudaFuncSetAttribute((const void*)gemm_hmma<3,1>, cudaFuncAttributeMaxDynamicSharedMemorySize, SMEM1);
    cudaFuncSetAttribute((const void*)gemm_hmma<4,2>, cudaFuncAttributeMaxDynamicSharedMemorySize, SMEM2);

    __half *xh,*xl,*wqh,*wql,*wkh,*wkl,*wvt,*wot;
    __half *qh,*ql,*kh,*vt,*ah,*ch,*cl;
    cudaGetSymbolAddress((void**)&xh,  g_xh);  cudaGetSymbolAddress((void**)&xl,  g_xl);
    cudaGetSymbolAddress((void**)&wqh, g_wqh); cudaGetSymbolAddress((void**)&wql, g_wql);
    cudaGetSymbolAddress((void**)&wkh, g_wkh); cudaGetSymbolAddress((void**)&wkl, g_wkl);
    cudaGetSymbolAddress((void**)&wvt, g_wvt); cudaGetSymbolAddress((void**)&wot, g_wot);
    cudaGetSymbolAddress((void**)&qh,  g_qh);  cudaGetSymbolAddress((void**)&ql,  g_ql);
    cudaGetSymbolAddress((void**)&kh,  g_kh);
    cudaGetSymbolAddress((void**)&vt,  g_vt);
    cudaGetSymbolAddress((void**)&ah,  g_ah);
    cudaGetSymbolAddress((void**)&ch,  g_ch);  cudaGetSymbolAddress((void**)&cl,  g_cl);

    // 1. prep
    split_kernel<<<OUT_ELEMS/256, 256>>>(x, xh, xl, OUT_ELEMS);
    dim3 tg(32, 32);
    splitT2_kernel<<<dim3(32,32,2), tg>>>(Wq, Wk, wqh, wql, wkh, wkl);
    cvtT2_kernel<<<dim3(32,32,2), tg>>>(Wv, Wo, wvt, wot);

    dim3 gProj(8, 64, 1);

    // 2. V proj (1-product)
    GP pv{};
    pv.Ah = xh; pv.Bh = wvt;
    pv.strideAz = 0; pv.strideBz = 0;
    pv.lda = 1024; pv.ldb = 1024; pv.K = 1024;
    pv.bias = bv; pv.scale = 1.f; pv.outH = vt;
    gemm_hmma<1,1><<<gProj, 256, SMEM1>>>(pv);

    // 3. Q proj (3-product: fp32 main + 2 fp16-acc corr, split output)
    GP p{};
    p.Ah = xh; p.Al = xl; p.lda = 1024; p.ldb = 1024; p.K = 1024;
    p.strideAz = 0; p.strideBz = 0; p.scale = 1.f;
    p.Bh = wqh; p.Bl = wql; p.bias = bq; p.outH = qh; p.outL = ql;
    gemm_hmma<0,3><<<gProj, 256, SMEM3>>>(p);

    // 4. K proj (2-product: fp32 main + 1 fp16-acc corr, single fp16 output)
    GP pk{};
    pk.Ah = xh; pk.Al = xl; pk.Bh = wkh;
    pk.strideAz = 0; pk.strideBz = 0;
    pk.lda = 1024; pk.ldb = 1024; pk.K = 1024;
    pk.bias = bk; pk.scale = 1.f; pk.outH = kh;
    gemm_hmma<5,2><<<gProj, 256, SMEM2>>>(pk);

    // 5. scores (2-product): A = q split, B = k single, K=128
    GP ps{};
    ps.Ah = qh; ps.Al = ql; ps.Bh = kh;
    ps.strideAz = NDIM*DDIM; ps.strideBz = NDIM*DDIM;
    ps.lda = 128; ps.ldb = 128; ps.K = 128;
    ps.scale = 0.088388347648318440550f;
    ps.outF = attn;
    gemm_hmma<2,2><<<dim3(8, 8, HEADS), 256, SMEM2>>>(ps);

    // 6. entmax (in place) + single fp16 split
    entmax_kernel<<<8192, 256>>>(attn, ah);

    // 7. ctx (1-product): A = attn fp16, B = vT, K=1024
    GP pc{};
    pc.Ah = ah; pc.Bh = vt;
    pc.strideAz = (long long)NDIM*NDIM; pc.strideBz = DDIM*NDIM;
    pc.lda = 1024; pc.ldb = 1024; pc.K = 1024;
    pc.scale = 1.f; pc.outH = ch; pc.outL = cl;
    gemm_hmma<3,1><<<dim3(1, 8, HEADS), 256, SMEM1>>>(pc);

    // 8. out proj (2-product)
    GP po{};
    po.Ah = ch; po.Al = cl; po.Bh = wot;
    po.strideAz = 0; po.strideBz = 0;
    po.lda = 1024; po.ldb = 1024; po.K = 1024;
    po.scale = 1.f; po.bias = bo; po.outF = out;
    gemm_hmma<4,2><<<gProj, 256, SMEM2>>>(po);
}

// round 16
// speedup vs baseline: 1.0929x; 1.0929x over previous
#include <cuda_runtime.h>
#include <cuda_fp16.h>
#include <cstdint>

// ===========================================================================
// EntmaxAttention B=8, N=1024, C=1024, H=8, D=128, alpha=1.5
// out  = [8,1024,1024]   -> d_out[0..8388608)
// attn = [8,8,1024,1024] -> d_out[8388608..75497472)
//
// Base sm_103: GEMMs via mma.sync m16n8k16 fp16 (HMMA), fp32 accum (R14 cfg).
// Q proj: split x split (3 products, BK=32). K proj: split x single
//   (2 products, single fp16 out). scores: q-split x k-single (2 products).
// V proj / ctx: single (1 product). out proj: split x single (2 products).
// Entmax: 6 bisection + 3 Newton steps (monotone-from-below, convex f).
// ===========================================================================

#define BDIM 8
#define HDIM 8
#define NDIM 1024
#define CDIM 1024
#define DDIM 128
#define OUT_ELEMS (BDIM*NDIM*CDIM)
#define HEADS (BDIM*HDIM)

__device__ __forceinline__ uint32_t smem_u32(const void* p) {
    uint32_t a;
    asm("{ .reg .u64 t; cvta.to.shared.u64 t, %1; cvt.u32.u64 %0, t; }"
        : "=r"(a) : "l"(p));
    return a;
}
__device__ __forceinline__ void cpa16(uint32_t dst, const void* src) {
    asm volatile("cp.async.cg.shared.global [%0], [%1], 16;" :: "r"(dst), "l"(src));
}
__device__ __forceinline__ void cpa_commit() {
    asm volatile("cp.async.commit_group;" ::: "memory");
}
template<int N>
__device__ __forceinline__ void cpa_wait() {
    asm volatile("cp.async.wait_group %0;" :: "n"(N) : "memory");
}
__device__ __forceinline__ void mma16816(float* d, const uint32_t* a, const uint32_t* b) {
    asm volatile("mma.sync.aligned.m16n8k16.row.col.f32.f16.f16.f32 "
        "{%0,%1,%2,%3}, {%4,%5,%6,%7}, {%8,%9}, {%0,%1,%2,%3};"
        : "+f"(d[0]), "+f"(d[1]), "+f"(d[2]), "+f"(d[3])
        : "r"(a[0]), "r"(a[1]), "r"(a[2]), "r"(a[3]), "r"(b[0]), "r"(b[1]));
}
__device__ __forceinline__ void ldm_x4(uint32_t* r, uint32_t addr) {
    asm volatile("ldmatrix.sync.aligned.m8n8.x4.shared.b16 {%0,%1,%2,%3}, [%4];"
        : "=r"(r[0]), "=r"(r[1]), "=r"(r[2]), "=r"(r[3]) : "r"(addr));
}

// ------------------------- scratch (device globals) ------------------------
__device__ __half g_xh[OUT_ELEMS],  g_xl[OUT_ELEMS];
__device__ __half g_wqh[CDIM*CDIM], g_wql[CDIM*CDIM];
__device__ __half g_wkh[CDIM*CDIM], g_wkl[CDIM*CDIM];
__device__ __half g_wvt[CDIM*CDIM];
__device__ __half g_wot[CDIM*CDIM];
__device__ __half g_qh[OUT_ELEMS],  g_ql[OUT_ELEMS];      // [BH,N,D] split
__device__ __half g_kh[OUT_ELEMS];                        // [BH,N,D] single
__device__ __half g_vt[OUT_ELEMS];                        // [BH,D,N] single
__device__ __half g_ah[(size_t)HEADS*NDIM*NDIM];          // attn fp16
__device__ __half g_ch[OUT_ELEMS],  g_cl[OUT_ELEMS];      // ctx [B,N,C] split

// ------------------------- prep kernels -------------------------------------
__global__ void __launch_bounds__(256) split_kernel(
    const float* __restrict__ src, __half* __restrict__ hi,
    __half* __restrict__ lo, int n)
{
    int i = blockIdx.x * 256 + threadIdx.x;
    if (i < n) {
        float v = src[i];
        __half h = __float2half(v);
        hi[i] = h;
        lo[i] = __float2half(v - __half2float(h));
    }
}

__global__ void __launch_bounds__(1024) splitT2_kernel(
    const float* __restrict__ W0, const float* __restrict__ W1,
    __half* __restrict__ h0, __half* __restrict__ l0,
    __half* __restrict__ h1, __half* __restrict__ l1)
{
    const float* W = blockIdx.z ? W1 : W0;
    __half* hiT = blockIdx.z ? h1 : h0;
    __half* loT = blockIdx.z ? l1 : l0;
    __shared__ float t[32][33];
    int bx = blockIdx.x * 32, by = blockIdx.y * 32;
    int x = threadIdx.x, y = threadIdx.y;
    t[y][x] = W[(size_t)(by + y) * CDIM + bx + x];
    __syncthreads();
    float v = t[x][y];
    __half h = __float2half(v);
    size_t o = (size_t)(bx + y) * CDIM + by + x;
    hiT[o] = h;
    loT[o] = __float2half(v - __half2float(h));
}

__global__ void __launch_bounds__(1024) cvtT2_kernel(
    const float* __restrict__ W0, const float* __restrict__ W1,
    __half* __restrict__ t0, __half* __restrict__ t1)
{
    const float* W = blockIdx.z ? W1 : W0;
    __half* hT = blockIdx.z ? t1 : t0;
    __shared__ float t[32][33];
    int bx = blockIdx.x * 32, by = blockIdx.y * 32;
    int x = threadIdx.x, y = threadIdx.y;
    t[y][x] = W[(size_t)(by + y) * CDIM + bx + x];
    __syncthreads();
    hT[(size_t)(bx + y) * CDIM + by + x] = __float2half(t[x][y]);
}

// ------------------------- generic HMMA GEMM (R14 config) -------------------
// D[m,n] = sum_k A[m,k]*B[n,k]  (both K-major), 128x128 CTA tile, 256 thr.
// NPROD 3: AhBh+AhBl+AlBh, BK=32, warp 64x32, NSTAGE=2 (80KB, 2 CTA/SM)
// NPROD 2: AhB+AlB,        BK=64, warp 32x64, NSTAGE=2 (110.6KB, 2 CTA/SM)
// NPROD 1: AB,             BK=64, warp 64x32, NSTAGE=3 (110.6KB, 2 CTA/SM)
// MODE 0: Q proj  -> hi/lo fp16 [B,H,N,D] (+bias)
// MODE 1: V proj  -> single fp16 vT [B,H,D,N] (+bias)
// MODE 2: scores  -> fp32*scale at outF[z<<20]
// MODE 3: ctx     -> hi/lo fp16 ctx [B,N,C]
// MODE 4: out proj-> fp32+bias at outF
// MODE 5: K proj  -> single fp16 [B,H,N,D] (+bias)
struct GP {
    const __half *Ah, *Al, *Bh, *Bl;
    long long strideAz, strideBz;
    int lda, ldb, K;
    const float* bias;
    float scale;
    float* outF;
    __half *outH, *outL;
};

template<int MODE, int NPROD>
__global__ void __launch_bounds__(256) gemm_hmma(GP p)
{
    constexpr int BK     = (NPROD == 3) ? 32 : 64;
    constexpr int KSTEPS = BK / 16;
    constexpr int ROWBk  = (NPROD == 3) ? 80 : 144;
    constexpr uint32_t TILEB = 128u * ROWBk;
    constexpr int NT = (NPROD == 3) ? 4 : ((NPROD == 2) ? 3 : 2);
    constexpr int NSTAGE = (NPROD == 1) ? 3 : 2;
    constexpr uint32_t STAGE = NT * TILEB;
    constexpr uint32_t BOFF = (NPROD == 1) ? TILEB : 2u * TILEB;
    constexpr int CPR = BK / 8;
    constexpr int WM = (NPROD == 2) ? 2 : 4;
    constexpr int WN = (NPROD == 2) ? 8 : 4;

    extern __shared__ char smem[];
    const uint32_t sbase = smem_u32(smem);
    const int tid = threadIdx.x;
    const int wid = tid >> 5;
    const int lane = tid & 31;
    const int g = lane >> 2;
    const int tq = lane & 3;
    const int warp_m = (NPROD == 2) ? (wid & 3) * 32 : (wid >> 2) * 64;
    const int warp_n = (NPROD == 2) ? (wid >> 2) * 64 : (wid & 3) * 32;
    const int z = blockIdx.z;
    const int row0 = blockIdx.y * 128;
    const int col0 = blockIdx.x * 128;

    const __half* Ah = p.Ah + (size_t)z * p.strideAz;
    const __half* Al = (NPROD >= 2) ? (p.Al + (size_t)z * p.strideAz) : nullptr;
    const __half* Bh = p.Bh + (size_t)z * p.strideBz;
    const __half* Bl = (NPROD == 3) ? (p.Bl + (size_t)z * p.strideBz) : nullptr;

    float acc[WM][WN][4];
    #pragma unroll
    for (int i = 0; i < WM; i++)
        #pragma unroll
        for (int j = 0; j < WN; j++)
            #pragma unroll
            for (int e = 0; e < 4; e++) acc[i][j][e] = 0.f;

    const int nchunk = p.K / BK;

    const uint32_t a_off = (uint32_t)((warp_m + (lane & 15)) * ROWBk + (lane >> 4) * 16);
    const uint32_t b_off = (uint32_t)((warp_n + (lane & 7) + ((lane >> 4) << 3)) * ROWBk
                                      + ((lane >> 3) & 1) * 16);

    auto prefetch = [&](int c) {
        int s = c % NSTAGE;
        int k0 = c * BK;
        uint32_t sb = sbase + s * STAGE;
        #pragma unroll
        for (int it = 0; it < KSTEPS; it++) {
            int id = tid + it * 256;
            int r = id / CPR;
            int ch = id % CPR;
            uint32_t doff = (uint32_t)(r * ROWBk + ch * 16);
            size_t ga = (size_t)(row0 + r) * p.lda + k0 + ch * 8;
            size_t gb = (size_t)(col0 + r) * p.ldb + k0 + ch * 8;
            cpa16(sb + doff, Ah + ga);
            if (NPROD >= 2) cpa16(sb + TILEB + doff, Al + ga);
            cpa16(sb + BOFF + doff, Bh + gb);
            if (NPROD == 3) cpa16(sb + BOFF + TILEB + doff, Bl + gb);
        }
        cpa_commit();
    };

    prefetch(0);
    if (NSTAGE == 3 && nchunk > 1) prefetch(1);

    for (int c = 0; c < nchunk; c++) {
        if (NSTAGE == 2) {
            cpa_wait<0>();
            __syncthreads();
            if (c + 1 < nchunk) prefetch(c + 1);
        } else {
            if (c + 1 < nchunk) cpa_wait<1>(); else cpa_wait<0>();
            __syncthreads();
            if (c + 2 < nchunk) prefetch(c + 2);
        }

        uint32_t stg = sbase + (uint32_t)((c % NSTAGE) * STAGE);

        #pragma unroll
        for (int s16 = 0; s16 < KSTEPS; s16++) {
            const uint32_t koffb = (uint32_t)(s16 * 32);

            uint32_t bh[WN][2], bl[WN][2];
            #pragma unroll
            for (int jp = 0; jp < WN/2; jp++) {
                uint32_t ba = stg + BOFF + b_off + koffb + (uint32_t)(jp * 16 * ROWBk);
                uint32_t r4[4];
                ldm_x4(r4, ba);
                bh[jp*2][0] = r4[0]; bh[jp*2][1] = r4[1];
                bh[jp*2+1][0] = r4[2]; bh[jp*2+1][1] = r4[3];
                if (NPROD == 3) {
                    ldm_x4(r4, ba + TILEB);
                    bl[jp*2][0] = r4[0]; bl[jp*2][1] = r4[1];
                    bl[jp*2+1][0] = r4[2]; bl[jp*2+1][1] = r4[3];
                }
            }

            uint32_t ahb[2][4], alb[2][4];
            {
                uint32_t aa = stg + a_off + koffb;
                ldm_x4(ahb[0], aa);
                if (NPROD >= 2) ldm_x4(alb[0], aa + TILEB);
            }
            #pragma unroll
            for (int i = 0; i < WM; i++) {
                const int cur = i & 1, nxt = cur ^ 1;
                if (i < WM - 1) {
                    uint32_t aa = stg + a_off + koffb + (uint32_t)((i + 1) * 16 * ROWBk);
                    ldm_x4(ahb[nxt], aa);
                    if (NPROD >= 2) ldm_x4(alb[nxt], aa + TILEB);
                }
                #pragma unroll
                for (int j = 0; j < WN; j++) {
                    mma16816(acc[i][j], ahb[cur], bh[j]);
                    if (NPROD == 3) mma16816(acc[i][j], ahb[cur], bl[j]);
                    if (NPROD >= 2) mma16816(acc[i][j], alb[cur], bh[j]);
                }
            }
        }
    }

    // --- epilogue (paired-column vector stores) ---
    #pragma unroll
    for (int i = 0; i < WM; i++) {
        #pragma unroll
        for (int j = 0; j < WN; j++) {
            #pragma unroll
            for (int eh = 0; eh < 2; eh++) {
                int m  = row0 + warp_m + i*16 + g + eh*8;
                int cc = col0 + warp_n + j*8 + tq*2;
                float v0 = acc[i][j][eh*2 + 0];
                float v1 = acc[i][j][eh*2 + 1];
                if (MODE == 0) {
                    v0 += p.bias[cc]; v1 += p.bias[cc + 1];
                    int b = m >> 10, nn = m & 1023;
                    int h = cc >> 7, d = cc & 127;
                    size_t o = ((size_t)(((b*8 + h) << 10) + nn)) * 128 + d;
                    __half h0 = __float2half(v0), h1 = __float2half(v1);
                    *(__half2*)&p.outH[o] = __halves2half2(h0, h1);
                    *(__half2*)&p.outL[o] = __halves2half2(
                        __float2half(v0 - __half2float(h0)),
                        __float2half(v1 - __half2float(h1)));
                } else if (MODE == 1) {
                    v0 += p.bias[cc]; v1 += p.bias[cc + 1];
                    int b = m >> 10, nn = m & 1023;
                    int h = cc >> 7, d = cc & 127;
                    size_t o = ((size_t)(((b*8 + h) << 7) + d)) * 1024 + nn;
                    p.outH[o] = __float2half(v0);
                    p.outH[o + 1024] = __float2half(v1);
                } else if (MODE == 2) {
                    float2 o2 = make_float2(v0 * p.scale, v1 * p.scale);
                    *(float2*)&p.outF[((size_t)z << 20) + (size_t)m * 1024 + cc] = o2;
                } else if (MODE == 3) {
                    int b = z >> 3, h = z & 7;
                    size_t o = ((size_t)((b << 10) + m)) * 1024 + h * 128 + cc;
                    __half h0 = __float2half(v0), h1 = __float2half(v1);
                    *(__half2*)&p.outH[o] = __halves2half2(h0, h1);
                    *(__half2*)&p.outL[o] = __halves2half2(
                        __float2half(v0 - __half2float(h0)),
                        __float2half(v1 - __half2float(h1)));
                } else if (MODE == 4) {
                    float2 o2 = make_float2(v0 + p.bias[cc], v1 + p.bias[cc + 1]);
                    *(float2*)&p.outF[(size_t)m * 1024 + cc] = o2;
                } else {  // MODE 5: K proj single fp16 [B,H,N,D]
                    v0 += p.bias[cc]; v1 += p.bias[cc + 1];
                    int b = m >> 10, nn = m & 1023;
                    int h = cc >> 7, d = cc & 127;
                    size_t o = ((size_t)(((b*8 + h) << 10) + nn)) * 128 + d;
                    *(__half2*)&p.outH[o] =
                        __halves2half2(__float2half(v0), __float2half(v1));
                }
            }
        }
    }
}

// ------------------------- entmax (bisect 6 + Newton 3) --------------------
// f(tau) = sum((xm-tau)+^2) - 1 is convex, C1, decreasing. After 6 bisection
// steps the bracket is 0.97/64 ~ 0.015 with f(tau_lo) >= 0 maintained.
// Newton from tau_lo: tangent of a convex f under-shoots -> monotone from
// below, never overshoots; 3 steps reach ~1e-11 (e' ~ e^2*sqrt(n_a)/2).
// g = sum(t+) >= (mx - root) > 0, so the division is safe.
__global__ void __launch_bounds__(256) entmax_kernel(
    float* __restrict__ attn, __half* __restrict__ ah)
{
    int gwarp = (blockIdx.x * blockDim.x + threadIdx.x) >> 5;
    int lane  = threadIdx.x & 31;
    size_t rbase = (size_t)gwarp * 1024;
    float* row = attn + rbase;
    const float4* rv = (const float4*)row;

    float xm[32];
    #pragma unroll
    for (int i = 0; i < 8; i++) {
        float4 v = rv[i*32 + lane];
        xm[i*4+0] = 0.5f * v.x; xm[i*4+1] = 0.5f * v.y;
        xm[i*4+2] = 0.5f * v.z; xm[i*4+3] = 0.5f * v.w;
    }

    float mx = xm[0];
    #pragma unroll
    for (int i = 1; i < 32; i++) mx = fmaxf(mx, xm[i]);
    #pragma unroll
    for (int o = 16; o > 0; o >>= 1)
        mx = fmaxf(mx, __shfl_xor_sync(0xffffffffu, mx, o));

    float tau_lo = mx - 1.0f;
    float dm = 1.0f - 0.03125f;

    float s0 = 0.f, s1 = 0.f, s2 = 0.f, s3 = 0.f;
    #pragma unroll
    for (int i = 0; i < 8; i++) {
        float t0 = fmaxf(xm[i*4+0] - tau_lo, 0.f);
        float t1 = fmaxf(xm[i*4+1] - tau_lo, 0.f);
        float t2 = fmaxf(xm[i*4+2] - tau_lo, 0.f);
        float t3 = fmaxf(xm[i*4+3] - tau_lo, 0.f);
        s0 = fmaf(t0, t0, s0); s1 = fmaf(t1, t1, s1);
        s2 = fmaf(t2, t2, s2); s3 = fmaf(t3, t3, s3);
    }
    float s = (s0 + s1) + (s2 + s3);
    #pragma unroll
    for (int o = 16; o > 0; o >>= 1)
        s += __shfl_xor_sync(0xffffffffu, s, o);
    float f_lo = s - 1.0f;

    // Phase 1: 6 bisection steps (keeps f(tau_lo) >= 0 invariant)
    #pragma unroll 1
    for (int it = 0; it < 6; it++) {
        dm *= 0.5f;
        float tau_m = tau_lo + dm;
        float f0 = 0.f, f1 = 0.f, f2 = 0.f, f3 = 0.f;
        #pragma unroll
        for (int i = 0; i < 8; i++) {
            float t0 = fmaxf(xm[i*4+0] - tau_m, 0.f);
            float t1 = fmaxf(xm[i*4+1] - tau_m, 0.f);
            float t2 = fmaxf(xm[i*4+2] - tau_m, 0.f);
            float t3 = fmaxf(xm[i*4+3] - tau_m, 0.f);
            f0 = fmaf(t0, t0, f0); f1 = fmaf(t1, t1, f1);
            f2 = fmaf(t2, t2, f2); f3 = fmaf(t3, t3, f3);
        }
        float fs = (f0 + f1) + (f2 + f3);
        #pragma unroll
        for (int o = 16; o > 0; o >>= 1)
            fs += __shfl_xor_sync(0xffffffffu, fs, o);
        if ((fs - 1.0f) * f_lo >= 0.f) tau_lo = tau_m;
    }

    // Phase 2: 3 Newton steps from tau_lo (monotone from below)
    float tau = tau_lo;
    #pragma unroll 1
    for (int it = 0; it < 3; it++) {
        float f0 = 0.f, f1 = 0.f, g0 = 0.f, g1 = 0.f;
        #pragma unroll
        for (int i = 0; i < 8; i++) {
            float t0 = fmaxf(xm[i*4+0] - tau, 0.f);
            float t1 = fmaxf(xm[i*4+1] - tau, 0.f);
            float t2 = fmaxf(xm[i*4+2] - tau, 0.f);
            float t3 = fmaxf(xm[i*4+3] - tau, 0.f);
            f0 = fmaf(t0, t0, f0); f1 = fmaf(t1, t1, f1);
            f0 = fmaf(t2, t2, f0); f1 = fmaf(t3, t3, f1);
            g0 += t0 + t2; g1 += t1 + t3;
        }
        float fs = f0 + f1;
        float gs = g0 + g1;
        #pragma unroll
        for (int o = 16; o > 0; o >>= 1) {
            fs += __shfl_xor_sync(0xffffffffu, fs, o);
            gs += __shfl_xor_sync(0xffffffffu, gs, o);
        }
        tau += (fs - 1.0f) / (2.0f * gs);
    }

    float pv[32];
    float psum = 0.f;
    #pragma unroll
    for (int i = 0; i < 32; i++) {
        float t = fmaxf(xm[i] - tau, 0.f);
        pv[i] = t * t;
        psum += pv[i];
    }
    #pragma unroll
    for (int o = 16; o > 0; o >>= 1)
        psum += __shfl_xor_sync(0xffffffffu, psum, o);
    float inv = 1.0f / psum;

    float4* wv = (float4*)row;
    #pragma unroll
    for (int i = 0; i < 8; i++) {
        float4 o;
        o.x = pv[i*4+0] * inv; o.y = pv[i*4+1] * inv;
        o.z = pv[i*4+2] * inv; o.w = pv[i*4+3] * inv;
        wv[i*32 + lane] = o;
        __half2 h01 = __halves2half2(__float2half(o.x), __float2half(o.y));
        __half2 h23 = __halves2half2(__float2half(o.z), __float2half(o.w));
        size_t hi = rbase + (size_t)i*128 + lane*4;
        *(__half2*)&ah[hi]     = h01;
        *(__half2*)&ah[hi + 2] = h23;
    }
}

// ---------------------------------------------------------------------------
extern "C" void kernel_launch(void* const* d_in, const int* in_sizes, int n_in,
                              void* d_out, int out_size)
{
    const float* x  = (const float*)d_in[0];
    const float* Wq = (const float*)d_in[1];
    const float* bq = (const float*)d_in[2];
    const float* Wk = (const float*)d_in[3];
    const float* bk = (const float*)d_in[4];
    const float* Wv = (const float*)d_in[5];
    const float* bv = (const float*)d_in[6];
    const float* Wo = (const float*)d_in[7];
    const float* bo = (const float*)d_in[8];

    float* out  = (float*)d_out;
    float* attn = out + OUT_ELEMS;

    const int SMEM3 = 2 * 4 * 10240;   // 81920   (2 CTA/SM)
    const int SMEM2 = 2 * 3 * 18432;   // 110592  (2 CTA/SM)
    const int SMEM1 = 3 * 2 * 18432;   // 110592  (2 CTA/SM)
    cudaFuncSetAttribute((const void*)gemm_hmma<0,3>, cudaFuncAttributeMaxDynamicSharedMemorySize, SMEM3);
    cudaFuncSetAttribute((const void*)gemm_hmma<5,2>, cudaFuncAttributeMaxDynamicSharedMemorySize, SMEM2);
    cudaFuncSetAttribute((const void*)gemm_hmma<1,1>, cudaFuncAttributeMaxDynamicSharedMemorySize, SMEM1);
    cudaFuncSetAttribute((const void*)gemm_hmma<2,2>, cudaFuncAttributeMaxDynamicSharedMemorySize, SMEM2);
    cudaFuncSetAttribute((const void*)gemm_hmma<3,1>, cudaFuncAttributeMaxDynamicSharedMemorySize, SMEM1);
    cudaFuncSetAttribute((const void*)gemm_hmma<4,2>, cudaFuncAttributeMaxDynamicSharedMemorySize, SMEM2);

    __half *xh,*xl,*wqh,*wql,*wkh,*wkl,*wvt,*wot;
    __half *qh,*ql,*kh,*vt,*ah,*ch,*cl;
    cudaGetSymbolAddress((void**)&xh,  g_xh);  cudaGetSymbolAddress((void**)&xl,  g_xl);
    cudaGetSymbolAddress((void**)&wqh, g_wqh); cudaGetSymbolAddress((void**)&wql, g_wql);
    cudaGetSymbolAddress((void**)&wkh, g_wkh); cudaGetSymbolAddress((void**)&wkl, g_wkl);
    cudaGetSymbolAddress((void**)&wvt, g_wvt); cudaGetSymbolAddress((void**)&wot, g_wot);
    cudaGetSymbolAddress((void**)&qh,  g_qh);  cudaGetSymbolAddress((void**)&ql,  g_ql);
    cudaGetSymbolAddress((void**)&kh,  g_kh);
    cudaGetSymbolAddress((void**)&vt,  g_vt);
    cudaGetSymbolAddress((void**)&ah,  g_ah);
    cudaGetSymbolAddress((void**)&ch,  g_ch);  cudaGetSymbolAddress((void**)&cl,  g_cl);

    // 1. prep
    split_kernel<<<OUT_ELEMS/256, 256>>>(x, xh, xl, OUT_ELEMS);
    dim3 tg(32, 32);
    splitT2_kernel<<<dim3(32,32,2), tg>>>(Wq, Wk, wqh, wql, wkh, wkl);
    cvtT2_kernel<<<dim3(32,32,2), tg>>>(Wv, Wo, wvt, wot);

    dim3 gProj(8, 64, 1);

    // 2. V proj (1-product)
    GP pv{};
    pv.Ah = xh; pv.Bh = wvt;
    pv.strideAz = 0; pv.strideBz = 0;
    pv.lda = 1024; pv.ldb = 1024; pv.K = 1024;
    pv.bias = bv; pv.scale = 1.f; pv.outH = vt;
    gemm_hmma<1,1><<<gProj, 256, SMEM1>>>(pv);

    // 3. Q proj (3-product, split output)
    GP p{};
    p.Ah = xh; p.Al = xl; p.lda = 1024; p.ldb = 1024; p.K = 1024;
    p.strideAz = 0; p.strideBz = 0; p.scale = 1.f;
    p.Bh = wqh; p.Bl = wql; p.bias = bq; p.outH = qh; p.outL = ql;
    gemm_hmma<0,3><<<gProj, 256, SMEM3>>>(p);

    // 4. K proj (2-product, single fp16 output)
    GP pk{};
    pk.Ah = xh; pk.Al = xl; pk.Bh = wkh;
    pk.strideAz = 0; pk.strideBz = 0;
    pk.lda = 1024; pk.ldb = 1024; pk.K = 1024;
    pk.bias = bk; pk.scale = 1.f; pk.outH = kh;
    gemm_hmma<5,2><<<gProj, 256, SMEM2>>>(pk);

    // 5. scores (2-product): A = q split, B = k single, K=128
    GP ps{};
    ps.Ah = qh; ps.Al = ql; ps.Bh = kh;
    ps.strideAz = NDIM*DDIM; ps.strideBz = NDIM*DDIM;
    ps.lda = 128; ps.ldb = 128; ps.K = 128;
    ps.scale = 0.088388347648318440550f;
    ps.outF = attn;
    gemm_hmma<2,2><<<dim3(8, 8, HEADS), 256, SMEM2>>>(ps);

    // 6. entmax (in place) + single fp16 split
    entmax_kernel<<<8192, 256>>>(attn, ah);

    // 7. ctx (1-product): A = attn fp16, B = vT, K=1024
    GP pc{};
    pc.Ah = ah; pc.Bh = vt;
    pc.strideAz = (long long)NDIM*NDIM; pc.strideBz = DDIM*NDIM;
    pc.lda = 1024; pc.ldb = 1024; pc.K = 1024;
    pc.scale = 1.f; pc.outH = ch; pc.outL = cl;
    gemm_hmma<3,1><<<dim3(1, 8, HEADS), 256, SMEM1>>>(pc);

    // 8. out proj (2-product)
    GP po{};
    po.Ah = ch; po.Al = cl; po.Bh = wot;
    po.strideAz = 0; po.strideBz = 0;
    po.lda = 1024; po.ldb = 1024; po.K = 1024;
    po.scale = 1.f; po.bias = bo; po.outF = out;
    gemm_hmma<4,2><<<gProj, 256, SMEM2>>>(po);
}

// round 17
// speedup vs baseline: 1.1557x; 1.0575x over previous
#include <cuda_runtime.h>
#include <cuda_fp16.h>
#include <cstdint>

// ===========================================================================
// EntmaxAttention B=8, N=1024, C=1024, H=8, D=128, alpha=1.5
// out  = [8,1024,1024]   -> d_out[0..8388608)
// attn = [8,8,1024,1024] -> d_out[8388608..75497472)
//
// Base sm_103: GEMMs via mma.sync m16n8k16 fp16 (HMMA), fp32 accum.
// Q proj: split x split (3 products, BK=32). K proj: split x single
//   (2 products, single fp16 out). scores: q-split x k-single (2 products).
// V proj / ctx / out proj: single x single (1 product).
// Entmax: 6 bisection + 3 Newton steps (monotone-from-below, convex f).
// ===========================================================================

#define BDIM 8
#define HDIM 8
#define NDIM 1024
#define CDIM 1024
#define DDIM 128
#define OUT_ELEMS (BDIM*NDIM*CDIM)
#define HEADS (BDIM*HDIM)

__device__ __forceinline__ uint32_t smem_u32(const void* p) {
    uint32_t a;
    asm("{ .reg .u64 t; cvta.to.shared.u64 t, %1; cvt.u32.u64 %0, t; }"
        : "=r"(a) : "l"(p));
    return a;
}
__device__ __forceinline__ void cpa16(uint32_t dst, const void* src) {
    asm volatile("cp.async.cg.shared.global [%0], [%1], 16;" :: "r"(dst), "l"(src));
}
__device__ __forceinline__ void cpa_commit() {
    asm volatile("cp.async.commit_group;" ::: "memory");
}
template<int N>
__device__ __forceinline__ void cpa_wait() {
    asm volatile("cp.async.wait_group %0;" :: "n"(N) : "memory");
}
__device__ __forceinline__ void mma16816(float* d, const uint32_t* a, const uint32_t* b) {
    asm volatile("mma.sync.aligned.m16n8k16.row.col.f32.f16.f16.f32 "
        "{%0,%1,%2,%3}, {%4,%5,%6,%7}, {%8,%9}, {%0,%1,%2,%3};"
        : "+f"(d[0]), "+f"(d[1]), "+f"(d[2]), "+f"(d[3])
        : "r"(a[0]), "r"(a[1]), "r"(a[2]), "r"(a[3]), "r"(b[0]), "r"(b[1]));
}
__device__ __forceinline__ void ldm_x4(uint32_t* r, uint32_t addr) {
    asm volatile("ldmatrix.sync.aligned.m8n8.x4.shared.b16 {%0,%1,%2,%3}, [%4];"
        : "=r"(r[0]), "=r"(r[1]), "=r"(r[2]), "=r"(r[3]) : "r"(addr));
}

// ------------------------- scratch (device globals) ------------------------
__device__ __half g_xh[OUT_ELEMS],  g_xl[OUT_ELEMS];
__device__ __half g_wqh[CDIM*CDIM], g_wql[CDIM*CDIM];
__device__ __half g_wkh[CDIM*CDIM], g_wkl[CDIM*CDIM];
__device__ __half g_wvt[CDIM*CDIM];
__device__ __half g_wot[CDIM*CDIM];
__device__ __half g_qh[OUT_ELEMS],  g_ql[OUT_ELEMS];      // [BH,N,D] split
__device__ __half g_kh[OUT_ELEMS];                        // [BH,N,D] single
__device__ __half g_vt[OUT_ELEMS];                        // [BH,D,N] single
__device__ __half g_ah[(size_t)HEADS*NDIM*NDIM];          // attn fp16
__device__ __half g_ch[OUT_ELEMS];                        // ctx [B,N,C] single

// ------------------------- prep kernels -------------------------------------
__global__ void __launch_bounds__(256) split_kernel(
    const float* __restrict__ src, __half* __restrict__ hi,
    __half* __restrict__ lo, int n)
{
    int i = blockIdx.x * 256 + threadIdx.x;
    if (i < n) {
        float v = src[i];
        __half h = __float2half(v);
        hi[i] = h;
        lo[i] = __float2half(v - __half2float(h));
    }
}

__global__ void __launch_bounds__(1024) splitT2_kernel(
    const float* __restrict__ W0, const float* __restrict__ W1,
    __half* __restrict__ h0, __half* __restrict__ l0,
    __half* __restrict__ h1, __half* __restrict__ l1)
{
    const float* W = blockIdx.z ? W1 : W0;
    __half* hiT = blockIdx.z ? h1 : h0;
    __half* loT = blockIdx.z ? l1 : l0;
    __shared__ float t[32][33];
    int bx = blockIdx.x * 32, by = blockIdx.y * 32;
    int x = threadIdx.x, y = threadIdx.y;
    t[y][x] = W[(size_t)(by + y) * CDIM + bx + x];
    __syncthreads();
    float v = t[x][y];
    __half h = __float2half(v);
    size_t o = (size_t)(bx + y) * CDIM + by + x;
    hiT[o] = h;
    loT[o] = __float2half(v - __half2float(h));
}

__global__ void __launch_bounds__(1024) cvtT2_kernel(
    const float* __restrict__ W0, const float* __restrict__ W1,
    __half* __restrict__ t0, __half* __restrict__ t1)
{
    const float* W = blockIdx.z ? W1 : W0;
    __half* hT = blockIdx.z ? t1 : t0;
    __shared__ float t[32][33];
    int bx = blockIdx.x * 32, by = blockIdx.y * 32;
    int x = threadIdx.x, y = threadIdx.y;
    t[y][x] = W[(size_t)(by + y) * CDIM + bx + x];
    __syncthreads();
    hT[(size_t)(bx + y) * CDIM + by + x] = __float2half(t[x][y]);
}

// ------------------------- generic HMMA GEMM --------------------------------
// D[m,n] = sum_k A[m,k]*B[n,k]  (both K-major), 128x128 CTA tile, 256 thr.
// NPROD 3: AhBh+AhBl+AlBh, BK=32, warp 64x32, NSTAGE=2 (80KB, 2 CTA/SM)
// NPROD 2: AhB+AlB,        BK=64, warp 32x64, NSTAGE=2 (110.6KB, 2 CTA/SM)
// NPROD 1: AB,             BK=64, warp 64x32, NSTAGE=3 (110.6KB, 2 CTA/SM)
// MODE 0: Q proj  -> hi/lo fp16 [B,H,N,D] (+bias)
// MODE 1: V proj  -> single fp16 vT [B,H,D,N] (+bias)
// MODE 2: scores  -> fp32*scale at outF[z<<20]
// MODE 3: ctx     -> single fp16 ctx [B,N,C]
// MODE 4: out proj-> fp32+bias at outF
// MODE 5: K proj  -> single fp16 [B,H,N,D] (+bias)
struct GP {
    const __half *Ah, *Al, *Bh, *Bl;
    long long strideAz, strideBz;
    int lda, ldb, K;
    const float* bias;
    float scale;
    float* outF;
    __half *outH, *outL;
};

template<int MODE, int NPROD>
__global__ void __launch_bounds__(256) gemm_hmma(GP p)
{
    constexpr int BK     = (NPROD == 3) ? 32 : 64;
    constexpr int KSTEPS = BK / 16;
    constexpr int ROWBk  = (NPROD == 3) ? 80 : 144;
    constexpr uint32_t TILEB = 128u * ROWBk;
    constexpr int NT = (NPROD == 3) ? 4 : ((NPROD == 2) ? 3 : 2);
    constexpr int NSTAGE = (NPROD == 1) ? 3 : 2;
    constexpr uint32_t STAGE = NT * TILEB;
    constexpr uint32_t BOFF = (NPROD == 1) ? TILEB : 2u * TILEB;
    constexpr int CPR = BK / 8;
    constexpr int WM = (NPROD == 2) ? 2 : 4;
    constexpr int WN = (NPROD == 2) ? 8 : 4;

    extern __shared__ char smem[];
    const uint32_t sbase = smem_u32(smem);
    const int tid = threadIdx.x;
    const int wid = tid >> 5;
    const int lane = tid & 31;
    const int g = lane >> 2;
    const int tq = lane & 3;
    const int warp_m = (NPROD == 2) ? (wid & 3) * 32 : (wid >> 2) * 64;
    const int warp_n = (NPROD == 2) ? (wid >> 2) * 64 : (wid & 3) * 32;
    const int z = blockIdx.z;
    const int row0 = blockIdx.y * 128;
    const int col0 = blockIdx.x * 128;

    const __half* Ah = p.Ah + (size_t)z * p.strideAz;
    const __half* Al = (NPROD >= 2) ? (p.Al + (size_t)z * p.strideAz) : nullptr;
    const __half* Bh = p.Bh + (size_t)z * p.strideBz;
    const __half* Bl = (NPROD == 3) ? (p.Bl + (size_t)z * p.strideBz) : nullptr;

    float acc[WM][WN][4];
    #pragma unroll
    for (int i = 0; i < WM; i++)
        #pragma unroll
        for (int j = 0; j < WN; j++)
            #pragma unroll
            for (int e = 0; e < 4; e++) acc[i][j][e] = 0.f;

    const int nchunk = p.K / BK;

    const uint32_t a_off = (uint32_t)((warp_m + (lane & 15)) * ROWBk + (lane >> 4) * 16);
    const uint32_t b_off = (uint32_t)((warp_n + (lane & 7) + ((lane >> 4) << 3)) * ROWBk
                                      + ((lane >> 3) & 1) * 16);

    auto prefetch = [&](int c) {
        int s = c % NSTAGE;
        int k0 = c * BK;
        uint32_t sb = sbase + s * STAGE;
        #pragma unroll
        for (int it = 0; it < KSTEPS; it++) {
            int id = tid + it * 256;
            int r = id / CPR;
            int ch = id % CPR;
            uint32_t doff = (uint32_t)(r * ROWBk + ch * 16);
            size_t ga = (size_t)(row0 + r) * p.lda + k0 + ch * 8;
            size_t gb = (size_t)(col0 + r) * p.ldb + k0 + ch * 8;
            cpa16(sb + doff, Ah + ga);
            if (NPROD >= 2) cpa16(sb + TILEB + doff, Al + ga);
            cpa16(sb + BOFF + doff, Bh + gb);
            if (NPROD == 3) cpa16(sb + BOFF + TILEB + doff, Bl + gb);
        }
        cpa_commit();
    };

    prefetch(0);
    if (NSTAGE == 3 && nchunk > 1) prefetch(1);

    for (int c = 0; c < nchunk; c++) {
        if (NSTAGE == 2) {
            cpa_wait<0>();
            __syncthreads();
            if (c + 1 < nchunk) prefetch(c + 1);
        } else {
            if (c + 1 < nchunk) cpa_wait<1>(); else cpa_wait<0>();
            __syncthreads();
            if (c + 2 < nchunk) prefetch(c + 2);
        }

        uint32_t stg = sbase + (uint32_t)((c % NSTAGE) * STAGE);

        #pragma unroll
        for (int s16 = 0; s16 < KSTEPS; s16++) {
            const uint32_t koffb = (uint32_t)(s16 * 32);

            uint32_t bh[WN][2], bl[WN][2];
            #pragma unroll
            for (int jp = 0; jp < WN/2; jp++) {
                uint32_t ba = stg + BOFF + b_off + koffb + (uint32_t)(jp * 16 * ROWBk);
                uint32_t r4[4];
                ldm_x4(r4, ba);
                bh[jp*2][0] = r4[0]; bh[jp*2][1] = r4[1];
                bh[jp*2+1][0] = r4[2]; bh[jp*2+1][1] = r4[3];
                if (NPROD == 3) {
                    ldm_x4(r4, ba + TILEB);
                    bl[jp*2][0] = r4[0]; bl[jp*2][1] = r4[1];
                    bl[jp*2+1][0] = r4[2]; bl[jp*2+1][1] = r4[3];
                }
            }

            uint32_t ahb[2][4], alb[2][4];
            {
                uint32_t aa = stg + a_off + koffb;
                ldm_x4(ahb[0], aa);
                if (NPROD >= 2) ldm_x4(alb[0], aa + TILEB);
            }
            #pragma unroll
            for (int i = 0; i < WM; i++) {
                const int cur = i & 1, nxt = cur ^ 1;
                if (i < WM - 1) {
                    uint32_t aa = stg + a_off + koffb + (uint32_t)((i + 1) * 16 * ROWBk);
                    ldm_x4(ahb[nxt], aa);
                    if (NPROD >= 2) ldm_x4(alb[nxt], aa + TILEB);
                }
                #pragma unroll
                for (int j = 0; j < WN; j++) {
                    mma16816(acc[i][j], ahb[cur], bh[j]);
                    if (NPROD == 3) mma16816(acc[i][j], ahb[cur], bl[j]);
                    if (NPROD >= 2) mma16816(acc[i][j], alb[cur], bh[j]);
                }
            }
        }
    }

    // --- epilogue (paired-column vector stores) ---
    #pragma unroll
    for (int i = 0; i < WM; i++) {
        #pragma unroll
        for (int j = 0; j < WN; j++) {
            #pragma unroll
            for (int eh = 0; eh < 2; eh++) {
                int m  = row0 + warp_m + i*16 + g + eh*8;
                int cc = col0 + warp_n + j*8 + tq*2;
                float v0 = acc[i][j][eh*2 + 0];
                float v1 = acc[i][j][eh*2 + 1];
                if (MODE == 0) {
                    v0 += p.bias[cc]; v1 += p.bias[cc + 1];
                    int b = m >> 10, nn = m & 1023;
                    int h = cc >> 7, d = cc & 127;
                    size_t o = ((size_t)(((b*8 + h) << 10) + nn)) * 128 + d;
                    __half h0 = __float2half(v0), h1 = __float2half(v1);
                    *(__half2*)&p.outH[o] = __halves2half2(h0, h1);
                    *(__half2*)&p.outL[o] = __halves2half2(
                        __float2half(v0 - __half2float(h0)),
                        __float2half(v1 - __half2float(h1)));
                } else if (MODE == 1) {
                    v0 += p.bias[cc]; v1 += p.bias[cc + 1];
                    int b = m >> 10, nn = m & 1023;
                    int h = cc >> 7, d = cc & 127;
                    size_t o = ((size_t)(((b*8 + h) << 7) + d)) * 1024 + nn;
                    p.outH[o] = __float2half(v0);
                    p.outH[o + 1024] = __float2half(v1);
                } else if (MODE == 2) {
                    float2 o2 = make_float2(v0 * p.scale, v1 * p.scale);
                    *(float2*)&p.outF[((size_t)z << 20) + (size_t)m * 1024 + cc] = o2;
                } else if (MODE == 3) {
                    int b = z >> 3, h = z & 7;
                    size_t o = ((size_t)((b << 10) + m)) * 1024 + h * 128 + cc;
                    *(__half2*)&p.outH[o] =
                        __halves2half2(__float2half(v0), __float2half(v1));
                } else if (MODE == 4) {
                    float2 o2 = make_float2(v0 + p.bias[cc], v1 + p.bias[cc + 1]);
                    *(float2*)&p.outF[(size_t)m * 1024 + cc] = o2;
                } else {  // MODE 5: K proj single fp16 [B,H,N,D]
                    v0 += p.bias[cc]; v1 += p.bias[cc + 1];
                    int b = m >> 10, nn = m & 1023;
                    int h = cc >> 7, d = cc & 127;
                    size_t o = ((size_t)(((b*8 + h) << 10) + nn)) * 128 + d;
                    *(__half2*)&p.outH[o] =
                        __halves2half2(__float2half(v0), __float2half(v1));
                }
            }
        }
    }
}

// ------------------------- entmax (bisect 6 + Newton 3) --------------------
__global__ void __launch_bounds__(256) entmax_kernel(
    float* __restrict__ attn, __half* __restrict__ ah)
{
    int gwarp = (blockIdx.x * blockDim.x + threadIdx.x) >> 5;
    int lane  = threadIdx.x & 31;
    size_t rbase = (size_t)gwarp * 1024;
    float* row = attn + rbase;
    const float4* rv = (const float4*)row;

    float xm[32];
    #pragma unroll
    for (int i = 0; i < 8; i++) {
        float4 v = rv[i*32 + lane];
        xm[i*4+0] = 0.5f * v.x; xm[i*4+1] = 0.5f * v.y;
        xm[i*4+2] = 0.5f * v.z; xm[i*4+3] = 0.5f * v.w;
    }

    float mx = xm[0];
    #pragma unroll
    for (int i = 1; i < 32; i++) mx = fmaxf(mx, xm[i]);
    #pragma unroll
    for (int o = 16; o > 0; o >>= 1)
        mx = fmaxf(mx, __shfl_xor_sync(0xffffffffu, mx, o));

    float tau_lo = mx - 1.0f;
    float dm = 1.0f - 0.03125f;

    float s0 = 0.f, s1 = 0.f, s2 = 0.f, s3 = 0.f;
    #pragma unroll
    for (int i = 0; i < 8; i++) {
        float t0 = fmaxf(xm[i*4+0] - tau_lo, 0.f);
        float t1 = fmaxf(xm[i*4+1] - tau_lo, 0.f);
        float t2 = fmaxf(xm[i*4+2] - tau_lo, 0.f);
        float t3 = fmaxf(xm[i*4+3] - tau_lo, 0.f);
        s0 = fmaf(t0, t0, s0); s1 = fmaf(t1, t1, s1);
        s2 = fmaf(t2, t2, s2); s3 = fmaf(t3, t3, s3);
    }
    float s = (s0 + s1) + (s2 + s3);
    #pragma unroll
    for (int o = 16; o > 0; o >>= 1)
        s += __shfl_xor_sync(0xffffffffu, s, o);
    float f_lo = s - 1.0f;

    // Phase 1: 6 bisection steps (keeps f(tau_lo) >= 0 invariant)
    #pragma unroll 1
    for (int it = 0; it < 6; it++) {
        dm *= 0.5f;
        float tau_m = tau_lo + dm;
        float f0 = 0.f, f1 = 0.f, f2 = 0.f, f3 = 0.f;
        #pragma unroll
        for (int i = 0; i < 8; i++) {
            float t0 = fmaxf(xm[i*4+0] - tau_m, 0.f);
            float t1 = fmaxf(xm[i*4+1] - tau_m, 0.f);
            float t2 = fmaxf(xm[i*4+2] - tau_m, 0.f);
            float t3 = fmaxf(xm[i*4+3] - tau_m, 0.f);
            f0 = fmaf(t0, t0, f0); f1 = fmaf(t1, t1, f1);
            f2 = fmaf(t2, t2, f2); f3 = fmaf(t3, t3, f3);
        }
        float fs = (f0 + f1) + (f2 + f3);
        #pragma unroll
        for (int o = 16; o > 0; o >>= 1)
            fs += __shfl_xor_sync(0xffffffffu, fs, o);
        if ((fs - 1.0f) * f_lo >= 0.f) tau_lo = tau_m;
    }

    // Phase 2: 3 Newton steps from tau_lo (monotone from below)
    float tau = tau_lo;
    #pragma unroll 1
    for (int it = 0; it < 3; it++) {
        float f0 = 0.f, f1 = 0.f, g0 = 0.f, g1 = 0.f;
        #pragma unroll
        for (int i = 0; i < 8; i++) {
            float t0 = fmaxf(xm[i*4+0] - tau, 0.f);
            float t1 = fmaxf(xm[i*4+1] - tau, 0.f);
            float t2 = fmaxf(xm[i*4+2] - tau, 0.f);
            float t3 = fmaxf(xm[i*4+3] - tau, 0.f);
            f0 = fmaf(t0, t0, f0); f1 = fmaf(t1, t1, f1);
            f0 = fmaf(t2, t2, f0); f1 = fmaf(t3, t3, f1);
            g0 += t0 + t2; g1 += t1 + t3;
        }
        float fs = f0 + f1;
        float gs = g0 + g1;
        #pragma unroll
        for (int o = 16; o > 0; o >>= 1) {
            fs += __shfl_xor_sync(0xffffffffu, fs, o);
            gs += __shfl_xor_sync(0xffffffffu, gs, o);
        }
        tau += (fs - 1.0f) / (2.0f * gs);
    }

    float pv[32];
    float psum = 0.f;
    #pragma unroll
    for (int i = 0; i < 32; i++) {
        float t = fmaxf(xm[i] - tau, 0.f);
        pv[i] = t * t;
        psum += pv[i];
    }
    #pragma unroll
    for (int o = 16; o > 0; o >>= 1)
        psum += __shfl_xor_sync(0xffffffffu, psum, o);
    float inv = 1.0f / psum;

    float4* wv = (float4*)row;
    #pragma unroll
    for (int i = 0; i < 8; i++) {
        float4 o;
        o.x = pv[i*4+0] * inv; o.y = pv[i*4+1] * inv;
        o.z = pv[i*4+2] * inv; o.w = pv[i*4+3] * inv;
        wv[i*32 + lane] = o;
        __half2 h01 = __halves2half2(__float2half(o.x), __float2half(o.y));
        __half2 h23 = __halves2half2(__float2half(o.z), __float2half(o.w));
        size_t hi = rbase + (size_t)i*128 + lane*4;
        *(__half2*)&ah[hi]     = h01;
        *(__half2*)&ah[hi + 2] = h23;
    }
}

// ---------------------------------------------------------------------------
extern "C" void kernel_launch(void* const* d_in, const int* in_sizes, int n_in,
                              void* d_out, int out_size)
{
    const float* x  = (const float*)d_in[0];
    const float* Wq = (const float*)d_in[1];
    const float* bq = (const float*)d_in[2];
    const float* Wk = (const float*)d_in[3];
    const float* bk = (const float*)d_in[4];
    const float* Wv = (const float*)d_in[5];
    const float* bv = (const float*)d_in[6];
    const float* Wo = (const float*)d_in[7];
    const float* bo = (const float*)d_in[8];

    float* out  = (float*)d_out;
    float* attn = out + OUT_ELEMS;

    const int SMEM3 = 2 * 4 * 10240;   // 81920   (2 CTA/SM)
    const int SMEM2 = 2 * 3 * 18432;   // 110592  (2 CTA/SM)
    const int SMEM1 = 3 * 2 * 18432;   // 110592  (2 CTA/SM)
    cudaFuncSetAttribute((const void*)gemm_hmma<0,3>, cudaFuncAttributeMaxDynamicSharedMemorySize, SMEM3);
    cudaFuncSetAttribute((const void*)gemm_hmma<5,2>, cudaFuncAttributeMaxDynamicSharedMemorySize, SMEM2);
    cudaFuncSetAttribute((const void*)gemm_hmma<1,1>, cudaFuncAttributeMaxDynamicSharedMemorySize, SMEM1);
    cudaFuncSetAttribute((const void*)gemm_hmma<2,2>, cudaFuncAttributeMaxDynamicSharedMemorySize, SMEM2);
    cudaFuncSetAttribute((const void*)gemm_hmma<3,1>, cudaFuncAttributeMaxDynamicSharedMemorySize, SMEM1);
    cudaFuncSetAttribute((const void*)gemm_hmma<4,1>, cudaFuncAttributeMaxDynamicSharedMemorySize, SMEM1);

    __half *xh,*xl,*wqh,*wql,*wkh,*wkl,*wvt,*wot;
    __half *qh,*ql,*kh,*vt,*ah,*ch;
    cudaGetSymbolAddress((void**)&xh,  g_xh);  cudaGetSymbolAddress((void**)&xl,  g_xl);
    cudaGetSymbolAddress((void**)&wqh, g_wqh); cudaGetSymbolAddress((void**)&wql, g_wql);
    cudaGetSymbolAddress((void**)&wkh, g_wkh); cudaGetSymbolAddress((void**)&wkl, g_wkl);
    cudaGetSymbolAddress((void**)&wvt, g_wvt); cudaGetSymbolAddress((void**)&wot, g_wot);
    cudaGetSymbolAddress((void**)&qh,  g_qh);  cudaGetSymbolAddress((void**)&ql,  g_ql);
    cudaGetSymbolAddress((void**)&kh,  g_kh);
    cudaGetSymbolAddress((void**)&vt,  g_vt);
    cudaGetSymbolAddress((void**)&ah,  g_ah);
    cudaGetSymbolAddress((void**)&ch,  g_ch);

    // 1. prep
    split_kernel<<<OUT_ELEMS/256, 256>>>(x, xh, xl, OUT_ELEMS);
    dim3 tg(32, 32);
    splitT2_kernel<<<dim3(32,32,2), tg>>>(Wq, Wk, wqh, wql, wkh, wkl);
    cvtT2_kernel<<<dim3(32,32,2), tg>>>(Wv, Wo, wvt, wot);

    dim3 gProj(8, 64, 1);

    // 2. V proj (1-product)
    GP pv{};
    pv.Ah = xh; pv.Bh = wvt;
    pv.strideAz = 0; pv.strideBz = 0;
    pv.lda = 1024; pv.ldb = 1024; pv.K = 1024;
    pv.bias = bv; pv.scale = 1.f; pv.outH = vt;
    gemm_hmma<1,1><<<gProj, 256, SMEM1>>>(pv);

    // 3. Q proj (3-product, split output)
    GP p{};
    p.Ah = xh; p.Al = xl; p.lda = 1024; p.ldb = 1024; p.K = 1024;
    p.strideAz = 0; p.strideBz = 0; p.scale = 1.f;
    p.Bh = wqh; p.Bl = wql; p.bias = bq; p.outH = qh; p.outL = ql;
    gemm_hmma<0,3><<<gProj, 256, SMEM3>>>(p);

    // 4. K proj (2-product, single fp16 output)
    GP pk{};
    pk.Ah = xh; pk.Al = xl; pk.Bh = wkh;
    pk.strideAz = 0; pk.strideBz = 0;
    pk.lda = 1024; pk.ldb = 1024; pk.K = 1024;
    pk.bias = bk; pk.scale = 1.f; pk.outH = kh;
    gemm_hmma<5,2><<<gProj, 256, SMEM2>>>(pk);

    // 5. scores (2-product): A = q split, B = k single, K=128
    GP ps{};
    ps.Ah = qh; ps.Al = ql; ps.Bh = kh;
    ps.strideAz = NDIM*DDIM; ps.strideBz = NDIM*DDIM;
    ps.lda = 128; ps.ldb = 128; ps.K = 128;
    ps.scale = 0.088388347648318440550f;
    ps.outF = attn;
    gemm_hmma<2,2><<<dim3(8, 8, HEADS), 256, SMEM2>>>(ps);

    // 6. entmax (in place) + single fp16 split
    entmax_kernel<<<8192, 256>>>(attn, ah);

    // 7. ctx (1-product, single fp16 output): A = attn fp16, B = vT, K=1024
    GP pc{};
    pc.Ah = ah; pc.Bh = vt;
    pc.strideAz = (long long)NDIM*NDIM; pc.strideBz = DDIM*NDIM;
    pc.lda = 1024; pc.ldb = 1024; pc.K = 1024;
    pc.scale = 1.f; pc.outH = ch;
    gemm_hmma<3,1><<<dim3(1, 8, HEADS), 256, SMEM1>>>(pc);

    // 8. out proj (1-product): A = ctx single, B = WoT single
    GP po{};
    po.Ah = ch; po.Bh = wot;
    po.strideAz = 0; po.strideBz = 0;
    po.lda = 1024; po.ldb = 1024; po.K = 1024;
    po.scale = 1.f; po.bias = bo; po.outF = out;
    gemm_hmma<4,1><<<gProj, 256, SMEM1>>>(po);
}